// round 8
// baseline (speedup 1.0000x reference)
#include <cuda_runtime.h>
#include <cuda_bf16.h>

// video [B=8, C=3, T=32, H=224, W=224] fp32.
// out[b,c,t,y,x] = clip01( clamped-bilinear sample of frame (b,c,t) at
//   src = (coord + shake + 0.5) * (224/240) - 0.5 )
// (trilinear resize 224->240 has identity T axis; jax boundary weight
//  renormalization for the linear kernel == coordinate clamping.)
//
// R7: R6 skeleton + register-batched gather for MLP.
//  - __launch_bounds__(224, 6): lift the 32-reg clamp so ptxas can keep
//    16 LDGs in flight per thread (R6 was MLP~2-4, DRAM-latency-bound).
//  - Gather loads batched in 2 waves of 8 rows (16 regs of tap data/wave).
//  - One __syncthreads; epilogue = aligned float4 LDS x2 + float4 STG.

#define HH 224
#define WW 224
#define TT 32
#define NPLANES 768                     // B*C*T
#define TILE_Y 16
#define TILES_PER_PLANE (HH / TILE_Y)   // 14
#define THREADS 224
#define SCALE_F (14.0f / 15.0f)

__global__ __launch_bounds__(THREADS, 6) void shake_bilinear_mlp_kernel(
    const float* __restrict__ vid,
    const int*   __restrict__ sh,
    const int*   __restrict__ sw,
    float*       __restrict__ out)
{
    __shared__ float hrow[TILE_Y][WW];   // 14336 B

    int blk  = blockIdx.x;
    int tile = blk % TILES_PER_PLANE;
    int p    = blk / TILES_PER_PLANE;    // plane = (b*C + c)*T + t
    int t    = p & (TT - 1);
    int sht  = __ldg(sh + t);
    int swt  = __ldg(sw + t);
    int yb   = tile * TILE_Y;
    int tid  = threadIdx.x;

    // Base source row for this tile (may be -1 at the top edge).
    float sy0  = ((float)(yb + sht) + 0.5f) * SCALE_F - 0.5f;
    int   base = (int)floorf(sy0);

    const float* plane = vid + (long long)p * (HH * WW);

    // ---- Gather + horizontal lerp, register-batched (2 waves x 8 rows) ----
    {
        int   x   = tid;                 // 0..223
        float sx  = ((float)(x + swt) + 0.5f) * SCALE_F - 0.5f;
        float f0  = floorf(sx);
        float fx  = sx - f0;
        int   x0  = (int)f0;
        int   x0c = max(x0, 0);
        int   x1c = min(x0 + 1, WW - 1);

#pragma unroll
        for (int w = 0; w < 2; w++) {
            float s0[8], s1[8];
#pragma unroll
            for (int r8 = 0; r8 < 8; r8++) {
                int r    = w * 8 + r8;
                int srcr = min(max(base + r, 0), HH - 1);
                const float* row = plane + srcr * WW;
                s0[r8] = __ldg(row + x0c);
                s1[r8] = __ldg(row + x1c);
            }
#pragma unroll
            for (int r8 = 0; r8 < 8; r8++) {
                hrow[w * 8 + r8][x] = fmaf(fx, s1[r8] - s0[r8], s0[r8]);
            }
        }
    }
    __syncthreads();

    // ---- Vertical lerp: aligned float4 LDS x2 per quad + float4 STG ----
    int x4 = tid % (WW / 4);             // 0..55
    int yy = tid / (WW / 4);             // 0..3
    int xb = x4 * 4;

    float4* outp = (float4*)(out + (long long)p * (HH * WW));
#pragma unroll
    for (int k = 0; k < 4; k++) {
        int   y   = yy + 4 * k;          // 0..15
        float sy  = ((float)(yb + y + sht) + 0.5f) * SCALE_F - 0.5f;
        float f0  = floorf(sy);
        float fy  = sy - f0;
        int   r0  = (int)f0 - base;      // in [0,14]; r0+1 <= 15 (clamped rows)

        float4 a = *(const float4*)(&hrow[r0][xb]);
        float4 b = *(const float4*)(&hrow[r0 + 1][xb]);

        float4 res;
        res.x = fminf(fmaxf(fmaf(fy, b.x - a.x, a.x), 0.0f), 1.0f);
        res.y = fminf(fmaxf(fmaf(fy, b.y - a.y, a.y), 0.0f), 1.0f);
        res.z = fminf(fmaxf(fmaf(fy, b.z - a.z, a.z), 0.0f), 1.0f);
        res.w = fminf(fmaxf(fmaf(fy, b.w - a.w, a.w), 0.0f), 1.0f);

        outp[(yb + y) * (WW / 4) + x4] = res;
    }
}

extern "C" void kernel_launch(void* const* d_in, const int* in_sizes, int n_in,
                              void* d_out, int out_size)
{
    const float* vid = (const float*)d_in[0];
    const int*   sh  = (const int*)d_in[1];
    const int*   sw  = (const int*)d_in[2];
    float*       out = (float*)d_out;

    int blocks = NPLANES * TILES_PER_PLANE; // 10752
    shake_bilinear_mlp_kernel<<<blocks, THREADS>>>(vid, sh, sw, out);
}